// round 2
// baseline (speedup 1.0000x reference)
#include <cuda_runtime.h>

#define DATA_DIM 512
#define BASIS_DIM 64
#define N_ROWS 2048
#define THREADS 128     // each thread handles 4 data dims (float4 load)
#define GRID 1024       // grid-stride: 2 rows per CTA

// Clamped open-uniform knots: t[g] = clamp(g-3, 0, 61) / 61, g in [0, 67]
__device__ __forceinline__ float knot(int g) {
    int j = g - 3;
    j = max(0, min(61, j));
    return (float)j * (1.0f / 61.0f);
}

__device__ __forceinline__ float bspline_dot(float xx, const float* __restrict__ Arow) {
    // span: m in [0, 60] such that interior[m] <= x < interior[m+1]
    int m = (int)(xx * 61.0f);
    m = max(0, min(60, m));
    int k = m + 3;  // global knot-span index

    float left1  = xx - knot(k);
    float left2  = xx - knot(k - 1);
    float left3  = xx - knot(k - 2);
    float right1 = knot(k + 1) - xx;
    float right2 = knot(k + 2) - xx;
    float right3 = knot(k + 3) - xx;

    // de Boor (NURBS Book A2.2), degree 3 fully unrolled.
    // Denominators are knot differences (> 0 in every reachable span), so
    // fast approximate division is safe and well within the 1e-3 gate.
    float N0 = 1.0f, N1, N2, N3, saved, temp;
    // p = 1
    temp = __fdividef(N0, right1 + left1);
    N0 = right1 * temp;
    N1 = left1 * temp;
    // p = 2
    temp = __fdividef(N0, right1 + left2);
    N0 = right1 * temp;
    saved = left2 * temp;
    temp = __fdividef(N1, right2 + left1);
    N1 = saved + right2 * temp;
    N2 = left1 * temp;
    // p = 3
    temp = __fdividef(N0, right1 + left3);
    N0 = right1 * temp;
    saved = left3 * temp;
    temp = __fdividef(N1, right2 + left2);
    N1 = saved + right2 * temp;
    saved = left2 * temp;
    temp = __fdividef(N2, right3 + left1);
    N2 = saved + right3 * temp;
    N3 = left1 * temp;

    // 4 nonzero basis funcs hit A[i, m..m+3]
    const float* a = Arow + m;
    return N0 * __ldg(a + 0) + N1 * __ldg(a + 1) + N2 * __ldg(a + 2) + N3 * __ldg(a + 3);
}

__global__ void __launch_bounds__(THREADS)
bspline_classifier_kernel(const float* __restrict__ x,
                          const float* __restrict__ A,
                          float* __restrict__ out) {
    const int tid = threadIdx.x;
    __shared__ float ws[THREADS / 32];

    for (int row = blockIdx.x; row < N_ROWS; row += gridDim.x) {
        // coalesced float4 load: thread tid covers data dims [4*tid, 4*tid+3]
        const float4 xv = reinterpret_cast<const float4*>(x + (size_t)row * DATA_DIM)[tid];
        const int i0 = tid * 4;

        float sum;
        sum  = bspline_dot(xv.x, A + (size_t)(i0 + 0) * BASIS_DIM);
        sum += bspline_dot(xv.y, A + (size_t)(i0 + 1) * BASIS_DIM);
        sum += bspline_dot(xv.z, A + (size_t)(i0 + 2) * BASIS_DIM);
        sum += bspline_dot(xv.w, A + (size_t)(i0 + 3) * BASIS_DIM);

        // warp reduction
        #pragma unroll
        for (int o = 16; o > 0; o >>= 1)
            sum += __shfl_xor_sync(0xFFFFFFFFu, sum, o);

        if ((tid & 31) == 0) ws[tid >> 5] = sum;
        __syncthreads();

        if (tid == 0) {
            float s = ws[0] + ws[1] + ws[2] + ws[3];
            out[row] = 1.0f / (1.0f + __expf(-s));
        }
        __syncthreads();  // protect ws before next iteration
    }
}

extern "C" void kernel_launch(void* const* d_in, const int* in_sizes, int n_in,
                              void* d_out, int out_size) {
    // Disambiguate by element count: x is 2048*512, A is 512*64.
    const float* x = (const float*)d_in[0];
    const float* A = (const float*)d_in[1];
    if (n_in >= 2 && in_sizes[0] == DATA_DIM * BASIS_DIM &&
        in_sizes[1] == N_ROWS * DATA_DIM) {
        x = (const float*)d_in[1];
        A = (const float*)d_in[0];
    }
    float* out = (float*)d_out;  // [2048]
    bspline_classifier_kernel<<<GRID, THREADS>>>(x, A, out);
}

// round 3
// speedup vs baseline: 1.0078x; 1.0078x over previous
#include <cuda_runtime.h>

#define DATA_DIM 512
#define BASIS_DIM 64
#define N_ROWS 2048
#define THREADS 128   // each thread handles 4 data dims (one float4 load)

// Clamped open-uniform knots: t[g] = clamp(g-3, 0, 61) / 61, g in [0, 67]
__device__ __forceinline__ float knot(int g) {
    int j = g - 3;
    j = max(0, min(61, j));
    return (float)j * (1.0f / 61.0f);
}

// de Boor weights for the 4 nonzero cubic basis functions on span m.
__device__ __forceinline__ float4 bspline_weights(float xx, int m) {
    int k = m + 3;  // global knot-span index

    float left1  = xx - knot(k);
    float left2  = xx - knot(k - 1);
    float left3  = xx - knot(k - 2);
    float right1 = knot(k + 1) - xx;
    float right2 = knot(k + 2) - xx;
    float right3 = knot(k + 3) - xx;

    float N0 = 1.0f, N1, N2, N3, saved, temp;
    // p = 1
    temp = __fdividef(N0, right1 + left1);
    N0 = right1 * temp;
    N1 = left1 * temp;
    // p = 2
    temp = __fdividef(N0, right1 + left2);
    N0 = right1 * temp;
    saved = left2 * temp;
    temp = __fdividef(N1, right2 + left1);
    N1 = saved + right2 * temp;
    N2 = left1 * temp;
    // p = 3
    temp = __fdividef(N0, right1 + left3);
    N0 = right1 * temp;
    saved = left3 * temp;
    temp = __fdividef(N1, right2 + left2);
    N1 = saved + right2 * temp;
    saved = left2 * temp;
    temp = __fdividef(N2, right3 + left1);
    N2 = saved + right3 * temp;
    N3 = left1 * temp;

    return make_float4(N0, N1, N2, N3);
}

__global__ void __launch_bounds__(THREADS, 4)
bspline_classifier_kernel(const float* __restrict__ x,
                          const float* __restrict__ A,
                          float* __restrict__ out) {
    const int row = blockIdx.x;
    const int tid = threadIdx.x;
    const int i0 = tid * 4;

    // coalesced float4 load: thread tid covers data dims [4*tid, 4*tid+3]
    const float4 xv = reinterpret_cast<const float4*>(x + (size_t)row * DATA_DIM)[tid];

    // ---- phase 1: span indices (cheap, unblocks the gathers) ----
    int m0 = max(0, min(60, (int)(xv.x * 61.0f)));
    int m1 = max(0, min(60, (int)(xv.y * 61.0f)));
    int m2 = max(0, min(60, (int)(xv.z * 61.0f)));
    int m3 = max(0, min(60, (int)(xv.w * 61.0f)));

    // ---- phase 2: issue all 16 A gathers up front (MLP) ----
    const float* a0 = A + (size_t)(i0 + 0) * BASIS_DIM + m0;
    const float* a1 = A + (size_t)(i0 + 1) * BASIS_DIM + m1;
    const float* a2 = A + (size_t)(i0 + 2) * BASIS_DIM + m2;
    const float* a3 = A + (size_t)(i0 + 3) * BASIS_DIM + m3;

    float v00 = __ldg(a0 + 0), v01 = __ldg(a0 + 1), v02 = __ldg(a0 + 2), v03 = __ldg(a0 + 3);
    float v10 = __ldg(a1 + 0), v11 = __ldg(a1 + 1), v12 = __ldg(a1 + 2), v13 = __ldg(a1 + 3);
    float v20 = __ldg(a2 + 0), v21 = __ldg(a2 + 1), v22 = __ldg(a2 + 2), v23 = __ldg(a2 + 3);
    float v30 = __ldg(a3 + 0), v31 = __ldg(a3 + 1), v32 = __ldg(a3 + 2), v33 = __ldg(a3 + 3);

    // ---- phase 3: basis weights (overlaps with loads in flight) ----
    float4 w0 = bspline_weights(xv.x, m0);
    float4 w1 = bspline_weights(xv.y, m1);
    float4 w2 = bspline_weights(xv.z, m2);
    float4 w3 = bspline_weights(xv.w, m3);

    // ---- phase 4: dot + reduce ----
    float sum = w0.x * v00 + w0.y * v01 + w0.z * v02 + w0.w * v03
              + w1.x * v10 + w1.y * v11 + w1.z * v12 + w1.w * v13
              + w2.x * v20 + w2.y * v21 + w2.z * v22 + w2.w * v23
              + w3.x * v30 + w3.y * v31 + w3.z * v32 + w3.w * v33;

    #pragma unroll
    for (int o = 16; o > 0; o >>= 1)
        sum += __shfl_xor_sync(0xFFFFFFFFu, sum, o);

    __shared__ float ws[THREADS / 32];
    if ((tid & 31) == 0) ws[tid >> 5] = sum;
    __syncthreads();

    if (tid == 0) {
        float s = ws[0] + ws[1] + ws[2] + ws[3];
        out[row] = 1.0f / (1.0f + __expf(-s));
    }
}

extern "C" void kernel_launch(void* const* d_in, const int* in_sizes, int n_in,
                              void* d_out, int out_size) {
    // Disambiguate by element count: x is 2048*512, A is 512*64.
    const float* x = (const float*)d_in[0];
    const float* A = (const float*)d_in[1];
    if (n_in >= 2 && in_sizes[0] == DATA_DIM * BASIS_DIM &&
        in_sizes[1] == N_ROWS * DATA_DIM) {
        x = (const float*)d_in[1];
        A = (const float*)d_in[0];
    }
    float* out = (float*)d_out;  // [2048]
    bspline_classifier_kernel<<<N_ROWS, THREADS>>>(x, A, out);
}